// round 1
// baseline (speedup 1.0000x reference)
#include <cuda_runtime.h>
#include <math.h>

#define NN 8192
#define NE 262144
#define CS 384
#define CZ 128
#define CH 16
#define HH 12
#define PQK 4
#define PV 8
#define PROJ_COLS 1152      // 192 q | 384 kv | 144 qp | 432 kvp
#define EDGE_COLS 44        // 12 b | 32 pz
#define FEAT_COLS 960
#define S_QK 0.14433756729740643f   // 1/sqrt(48)
#define S_B  0.5773502691896258f    // 1/sqrt(3)
#define S_PT 0.1360827634879543f    // 1/sqrt(54)
#define INF_C 100000.0f

// ---------------- scratch (static device memory; no allocation) ----------------
__device__ float g_proj[(size_t)NN * PROJ_COLS];
__device__ float g_qpts[(size_t)NN * HH * PQK * 3];
__device__ float g_kpts[(size_t)NN * HH * PQK * 3];
__device__ float g_vpts[(size_t)NN * HH * PV * 3];
__device__ float g_bpz[(size_t)NE * EDGE_COLS];
__device__ float g_abuf[(size_t)NE * HH];
__device__ float g_feats[(size_t)NN * FEAT_COLS];
__device__ int   g_perm[NE];
__device__ int   g_nodeOf[NE];
__device__ int   g_dstOf[NE];
__device__ int   g_hist[NN];
__device__ int   g_off[NN + 1];
__device__ int   g_cursor[NN];
__device__ float g_Wproj[CS * PROJ_COLS];
__device__ float g_Bproj[PROJ_COLS];
__device__ float g_Wedge[CZ * EDGE_COLS];
__device__ float g_Bedge[EDGE_COLS];

// ---------------- weight packing ----------------
#define PACK_W   (CS * PROJ_COLS)                 // 442368
#define PACK_B   PROJ_COLS                        // 1152
#define PACK_EW  (CZ * EDGE_COLS)                 // 5632
#define PACK_EB  EDGE_COLS                        // 44
#define PACK_TOTAL (PACK_W + PACK_B + PACK_EW + PACK_EB)

__global__ void k_pack(const float* __restrict__ q_w, const float* __restrict__ q_b,
                       const float* __restrict__ kv_w, const float* __restrict__ kv_b,
                       const float* __restrict__ qp_w, const float* __restrict__ qp_b,
                       const float* __restrict__ kvp_w, const float* __restrict__ kvp_b,
                       const float* __restrict__ b_w, const float* __restrict__ b_b,
                       const float* __restrict__ dz_w, const float* __restrict__ dz_b) {
    int gid = blockIdx.x * blockDim.x + threadIdx.x;
    if (gid < PACK_W) {
        int k = gid / PROJ_COLS, col = gid % PROJ_COLS;
        float v;
        if (col < 192)      v = q_w[k * 192 + col];
        else if (col < 576) v = kv_w[k * 384 + (col - 192)];
        else if (col < 720) v = qp_w[k * 144 + (col - 576)];
        else                v = kvp_w[k * 432 + (col - 720)];
        g_Wproj[gid] = v;
    } else if (gid < PACK_W + PACK_B) {
        int col = gid - PACK_W;
        float v;
        if (col < 192)      v = q_b[col];
        else if (col < 576) v = kv_b[col - 192];
        else if (col < 720) v = qp_b[col - 576];
        else                v = kvp_b[col - 720];
        g_Bproj[col] = v;
    } else if (gid < PACK_W + PACK_B + PACK_EW) {
        int idx = gid - PACK_W - PACK_B;
        int k = idx / EDGE_COLS, col = idx % EDGE_COLS;
        g_Wedge[idx] = (col < 12) ? b_w[k * 12 + col] : dz_w[k * 32 + (col - 12)];
    } else if (gid < PACK_TOTAL) {
        int col = gid - PACK_W - PACK_B - PACK_EW;
        g_Bedge[col] = (col < 12) ? b_b[col] : dz_b[col - 12];
    }
}

// ---------------- sorting: histogram / scan / scatter ----------------
__global__ void k_zero_hist() {
    int i = blockIdx.x * blockDim.x + threadIdx.x;
    if (i < NN) g_hist[i] = 0;
}
__global__ void k_hist(const int* __restrict__ edge_index) {
    int e = blockIdx.x * blockDim.x + threadIdx.x;
    if (e < NE) atomicAdd(&g_hist[edge_index[NE + e]], 1);   // src = row 1
}
__global__ void k_scan() {
    __shared__ int partial[1024];
    int tid = threadIdx.x;
    int base = tid * 8;
    int local[8];
    int s = 0;
    #pragma unroll
    for (int i = 0; i < 8; i++) { local[i] = g_hist[base + i]; s += local[i]; }
    partial[tid] = s;
    __syncthreads();
    for (int d = 1; d < 1024; d <<= 1) {
        int v = 0;
        if (tid >= d) v = partial[tid - d];
        __syncthreads();
        if (tid >= d) partial[tid] += v;
        __syncthreads();
    }
    int run = partial[tid] - s;   // exclusive
    #pragma unroll
    for (int i = 0; i < 8; i++) {
        g_off[base + i] = run;
        g_cursor[base + i] = run;
        run += local[i];
    }
    if (tid == 1023) g_off[NN] = run;
}
__global__ void k_scatter(const int* __restrict__ edge_index) {
    int e = blockIdx.x * blockDim.x + threadIdx.x;
    if (e >= NE) return;
    int src = edge_index[NE + e];
    int dst = edge_index[e];
    int pos = atomicAdd(&g_cursor[src], 1);
    g_perm[pos] = e;
    g_nodeOf[pos] = src;
    g_dstOf[pos] = dst;
}

// ---------------- generic tiled SGEMM (64x64x16, 256 threads, 4x4 microtile) ----------------
template <int M, int N, int K>
__device__ __forceinline__ void sgemm_body(const float* __restrict__ A,
                                           const float* __restrict__ W,
                                           const float* __restrict__ Bias,
                                           float* __restrict__ C) {
    __shared__ float As[16][64];
    __shared__ float Bs[16][64];
    const int tid = threadIdx.x;
    const int tx = tid & 15, ty = tid >> 4;
    const int row0 = blockIdx.y * 64, col0 = blockIdx.x * 64;
    float acc[4][4];
    #pragma unroll
    for (int i = 0; i < 4; i++)
        #pragma unroll
        for (int j = 0; j < 4; j++) acc[i][j] = 0.f;

    const int ar = tid >> 2;          // 0..63 row in tile
    const int ac = (tid & 3) * 4;     // col group

    for (int k0 = 0; k0 < K; k0 += 16) {
        float4 av = *reinterpret_cast<const float4*>(&A[(size_t)(row0 + ar) * K + k0 + ac]);
        As[ac + 0][ar] = av.x; As[ac + 1][ar] = av.y;
        As[ac + 2][ar] = av.z; As[ac + 3][ar] = av.w;
        #pragma unroll
        for (int l = 0; l < 4; l++) {
            int idx = tid + 256 * l;
            int kr = idx >> 6, cc = idx & 63;
            float v = 0.f;
            if (col0 + cc < N) v = W[(size_t)(k0 + kr) * N + col0 + cc];
            Bs[kr][cc] = v;
        }
        __syncthreads();
        #pragma unroll
        for (int kk = 0; kk < 16; kk++) {
            float4 a4 = *reinterpret_cast<const float4*>(&As[kk][ty * 4]);
            float4 b4 = *reinterpret_cast<const float4*>(&Bs[kk][tx * 4]);
            float aa[4] = {a4.x, a4.y, a4.z, a4.w};
            float bb[4] = {b4.x, b4.y, b4.z, b4.w};
            #pragma unroll
            for (int i = 0; i < 4; i++)
                #pragma unroll
                for (int j = 0; j < 4; j++) acc[i][j] += aa[i] * bb[j];
        }
        __syncthreads();
    }
    #pragma unroll
    for (int i = 0; i < 4; i++) {
        int row = row0 + ty * 4 + i;
        #pragma unroll
        for (int j = 0; j < 4; j++) {
            int col = col0 + tx * 4 + j;
            if (row < M && col < N) C[(size_t)row * N + col] = acc[i][j] + Bias[col];
        }
    }
}

__global__ void k_gemm_proj(const float* __restrict__ s) {
    sgemm_body<NN, PROJ_COLS, CS>(s, g_Wproj, g_Bproj, g_proj);
}
__global__ void k_gemm_edge(const float* __restrict__ z) {
    sgemm_body<NE, EDGE_COLS, CZ>(z, g_Wedge, g_Bedge, g_bpz);
}
__global__ void k_gemm_out(const float* __restrict__ out_w, const float* __restrict__ out_b,
                           float* __restrict__ out) {
    sgemm_body<NN, CS, FEAT_COLS>(g_feats, out_w, out_b, out);
}

// ---------------- point transform ----------------
// qp: y cols [576,720): pts[n,h,j,i] = sum_d rot[i,d]*y[d*48 + h*4+j] + trans[i]
// kvp: y cols [720,1152): xyz[p=h*12+j, i] = y[i*144 + p]
__global__ void k_pointify(const float* __restrict__ rot, const float* __restrict__ trans) {
    int gid = blockIdx.x * blockDim.x + threadIdx.x;
    if (gid >= NN * 192) return;
    int n = gid / 192;
    int p_all = gid % 192;
    const float* R = rot + (size_t)n * 9;
    const float* T = trans + (size_t)n * 3;
    const float* pr = g_proj + (size_t)n * PROJ_COLS;
    if (p_all < 48) {
        int p = p_all;
        float y0 = pr[576 + 0 * 48 + p];
        float y1 = pr[576 + 1 * 48 + p];
        float y2 = pr[576 + 2 * 48 + p];
        #pragma unroll
        for (int i = 0; i < 3; i++) {
            float v = R[i * 3 + 0] * y0 + R[i * 3 + 1] * y1 + R[i * 3 + 2] * y2 + T[i];
            g_qpts[((size_t)n * 48 + p) * 3 + i] = v;
        }
    } else {
        int p = p_all - 48;   // h*12 + j
        float y0 = pr[720 + 0 * 144 + p];
        float y1 = pr[720 + 1 * 144 + p];
        float y2 = pr[720 + 2 * 144 + p];
        int h = p / 12, j = p % 12;
        #pragma unroll
        for (int i = 0; i < 3; i++) {
            float v = R[i * 3 + 0] * y0 + R[i * 3 + 1] * y1 + R[i * 3 + 2] * y2 + T[i];
            if (j < PQK) g_kpts[((size_t)n * 48 + h * 4 + j) * 3 + i] = v;
            else         g_vpts[((size_t)n * 96 + h * 8 + (j - 4)) * 3 + i] = v;
        }
    }
}

// ---------------- per-(sorted-edge, head) attention logits ----------------
__global__ void k_logits(const float* __restrict__ mask, const float* __restrict__ head_weights) {
    int gid = blockIdx.x * blockDim.x + threadIdx.x;
    if (gid >= NE * HH) return;
    int t = gid / HH;
    int h = gid % HH;
    int n = g_nodeOf[t];
    int dst = g_dstOf[t];
    int e = g_perm[t];

    const float* qp = g_proj + (size_t)n * PROJ_COLS + h * 16;
    const float* kp = g_proj + (size_t)dst * PROJ_COLS + 192 + h * 32;
    float dot = 0.f;
    #pragma unroll
    for (int c = 0; c < CH; c++) dot += qp[c] * kp[c];

    float b = g_bpz[(size_t)e * EDGE_COLS + h];

    float pt = 0.f;
    const float* qq = g_qpts + ((size_t)n * 48 + h * 4) * 3;
    const float* kk = g_kpts + ((size_t)dst * 48 + h * 4) * 3;
    #pragma unroll
    for (int u = 0; u < PQK * 3; u++) {
        float d = qq[u] - kk[u];
        pt += d * d;
    }
    float hwv = log1pf(expf(head_weights[h])) * S_PT;
    float em = INF_C * (mask[dst] * mask[n] - 1.f);
    float a = dot * S_QK + S_B * b - 0.5f * hwv * pt + em;
    g_abuf[(size_t)t * HH + h] = a;
}

// ---------------- per-node softmax + aggregation + feature build ----------------
__global__ void k_node(const float* __restrict__ rot, const float* __restrict__ trans) {
    int n = blockIdx.x;
    int tid = threadIdx.x;
    int beg = g_off[n], end = g_off[n + 1];
    int dn = end - beg;

    __shared__ float sred[192];
    __shared__ float s_amax[HH], s_inv[HH];
    __shared__ float wch[64 * HH];
    __shared__ int dsh[64], esh[64];
    __shared__ float sacc[864];

    // --- max per head ---
    if (tid < 192) {
        int h = tid % HH, j = tid / HH;
        float m = -INFINITY;
        for (int i = j; i < dn; i += 16) m = fmaxf(m, g_abuf[(size_t)(beg + i) * HH + h]);
        sred[tid] = m;
    }
    __syncthreads();
    if (tid < HH) {
        float m = -INFINITY;
        #pragma unroll
        for (int j = 0; j < 16; j++) m = fmaxf(m, sred[j * HH + tid]);
        if (!isfinite(m)) m = 0.f;
        s_amax[tid] = m;
    }
    __syncthreads();
    // --- denom per head ---
    if (tid < 192) {
        int h = tid % HH, j = tid / HH;
        float am = s_amax[h];
        float s = 0.f;
        for (int i = j; i < dn; i += 16) s += expf(g_abuf[(size_t)(beg + i) * HH + h] - am);
        sred[tid] = s;
    }
    __syncthreads();
    if (tid < HH) {
        float s = 0.f;
        #pragma unroll
        for (int j = 0; j < 16; j++) s += sred[j * HH + tid];
        s_inv[tid] = 1.f / (s + 1e-16f);
    }
    __syncthreads();

    // --- component assignment (864 outputs over 256 threads, 4 each) ---
    float acc[4] = {0.f, 0.f, 0.f, 0.f};
    int typ[4], hsel[4], coff[4];
    #pragma unroll
    for (int k = 0; k < 4; k++) {
        int c = tid + 256 * k;
        if (c < 192) {                       // o: v[dst,h,cc]
            typ[k] = 0; hsel[k] = c / 16;
            coff[k] = 192 + (c / 16) * 32 + 16 + (c % 16);
        } else if (c < 480) {                // o_pt: v_pts[dst]
            int u = c - 192;
            typ[k] = 1; hsel[k] = u / 24; coff[k] = u;
        } else if (c < 864) {                // o_pair: pz[e]
            int u = c - 480;
            typ[k] = 2; hsel[k] = u / 32; coff[k] = 12 + (u % 32);
        } else { typ[k] = 3; hsel[k] = 0; coff[k] = 0; }
    }

    for (int c0 = 0; c0 < dn; c0 += 64) {
        int cn = min(64, dn - c0);
        __syncthreads();
        for (int t = tid; t < cn * HH; t += 256) {
            int i = t / HH, h = t % HH;
            wch[t] = expf(g_abuf[(size_t)(beg + c0 + i) * HH + h] - s_amax[h]) * s_inv[h];
        }
        if (tid < cn) {
            dsh[tid] = g_dstOf[beg + c0 + tid];
            esh[tid] = g_perm[beg + c0 + tid];
        }
        __syncthreads();
        for (int i = 0; i < cn; i++) {
            int dst = dsh[i];
            int e = esh[i];
            #pragma unroll
            for (int k = 0; k < 4; k++) {
                if (typ[k] == 3) continue;
                float v;
                if (typ[k] == 0)      v = g_proj[(size_t)dst * PROJ_COLS + coff[k]];
                else if (typ[k] == 1) v = g_vpts[(size_t)dst * 288 + coff[k]];
                else                  v = g_bpz[(size_t)e * EDGE_COLS + coff[k]];
                acc[k] += wch[i * HH + hsel[k]] * v;
            }
        }
    }

    #pragma unroll
    for (int k = 0; k < 4; k++) {
        int c = tid + 256 * k;
        if (c < 864) sacc[c] = acc[k];
    }
    __syncthreads();

    // --- finalize features ---
    float* f = g_feats + (size_t)n * FEAT_COLS;
    if (tid < 192) f[tid] = sacc[tid];
    for (int t = tid; t < 384; t += 256) f[576 + t] = sacc[480 + t];
    if (tid < 96) {
        int q = tid;
        float g0 = sacc[192 + q * 3 + 0] - trans[(size_t)n * 3 + 0];
        float g1 = sacc[192 + q * 3 + 1] - trans[(size_t)n * 3 + 1];
        float g2 = sacc[192 + q * 3 + 2] - trans[(size_t)n * 3 + 2];
        const float* R = rot + (size_t)n * 9;
        float l0 = R[0] * g0 + R[3] * g1 + R[6] * g2;
        float l1 = R[1] * g0 + R[4] * g1 + R[7] * g2;
        float l2 = R[2] * g0 + R[5] * g1 + R[8] * g2;
        f[192 + q] = l0;
        f[288 + q] = l1;
        f[384 + q] = l2;
        f[480 + q] = sqrtf(l0 * l0 + l1 * l1 + l2 * l2 + 1e-8f);
    }
}

// ---------------- launch ----------------
extern "C" void kernel_launch(void* const* d_in, const int* in_sizes, int n_in,
                              void* d_out, int out_size) {
    const float* s          = (const float*)d_in[0];
    const float* z          = (const float*)d_in[1];
    const int*   edge_index = (const int*)  d_in[2];
    const float* rot        = (const float*)d_in[3];
    const float* trans      = (const float*)d_in[4];
    const float* mask       = (const float*)d_in[5];
    const float* q_w        = (const float*)d_in[6];
    const float* q_b        = (const float*)d_in[7];
    const float* kv_w       = (const float*)d_in[8];
    const float* kv_b       = (const float*)d_in[9];
    const float* qp_w       = (const float*)d_in[10];
    const float* qp_b       = (const float*)d_in[11];
    const float* kvp_w      = (const float*)d_in[12];
    const float* kvp_b      = (const float*)d_in[13];
    const float* b_w        = (const float*)d_in[14];
    const float* b_b        = (const float*)d_in[15];
    const float* dz_w       = (const float*)d_in[16];
    const float* dz_b       = (const float*)d_in[17];
    const float* head_w     = (const float*)d_in[18];
    const float* out_w      = (const float*)d_in[19];
    const float* out_b      = (const float*)d_in[20];
    float* out = (float*)d_out;

    k_pack<<<(PACK_TOTAL + 255) / 256, 256>>>(q_w, q_b, kv_w, kv_b, qp_w, qp_b,
                                              kvp_w, kvp_b, b_w, b_b, dz_w, dz_b);
    k_zero_hist<<<NN / 256, 256>>>();
    k_hist<<<NE / 256, 256>>>(edge_index);
    k_scan<<<1, 1024>>>();
    k_scatter<<<NE / 256, 256>>>(edge_index);

    k_gemm_proj<<<dim3(PROJ_COLS / 64, NN / 64), 256>>>(s);
    k_pointify<<<(NN * 192) / 256, 256>>>(rot, trans);
    k_gemm_edge<<<dim3(1, NE / 64), 256>>>(z);
    k_logits<<<(NE * HH) / 256, 256>>>(mask, head_w);
    k_node<<<NN, 256>>>(rot, trans);
    k_gemm_out<<<dim3(CS / 64, NN / 64), 256>>>(out_w, out_b, out);
}

// round 2
// speedup vs baseline: 1.2320x; 1.2320x over previous
#include <cuda_runtime.h>
#include <math.h>

#define NN 8192
#define NE 262144
#define CS 384
#define CZ 128
#define CH 16
#define HH 12
#define PQK 4
#define PV 8
#define PROJ_COLS 1152      // 192 q | 384 kv | 144 qp | 432 kvp
#define EDGE_COLS 44        // 12 b | 32 pz
#define FEAT_COLS 960
#define S_QK 0.14433756729740643f   // 1/sqrt(48)
#define S_B  0.5773502691896258f    // 1/sqrt(3)
#define S_PT 0.1360827634879543f    // 1/sqrt(54)
#define INF_C 100000.0f

// ---------------- scratch (static device memory; no allocation) ----------------
__device__ float g_proj[(size_t)NN * PROJ_COLS];
__device__ float g_qpts[(size_t)NN * HH * PQK * 3];
__device__ float g_kpts[(size_t)NN * HH * PQK * 3];
__device__ float g_vpts[(size_t)NN * HH * PV * 3];
__device__ float g_bpz[(size_t)NE * EDGE_COLS];
__device__ float g_abuf[(size_t)NE * HH];
__device__ float g_feats[(size_t)NN * FEAT_COLS];
__device__ int   g_perm[NE];
__device__ int   g_nodeOf[NE];
__device__ int   g_dstOf[NE];
__device__ int   g_hist[NN];
__device__ int   g_off[NN + 1];
__device__ int   g_cursor[NN];
__device__ float g_Wproj[CS * PROJ_COLS];
__device__ float g_Bproj[PROJ_COLS];
__device__ float g_Wedge[CZ * EDGE_COLS];
__device__ float g_Bedge[EDGE_COLS];

// ---------------- weight packing ----------------
#define PACK_W   (CS * PROJ_COLS)
#define PACK_B   PROJ_COLS
#define PACK_EW  (CZ * EDGE_COLS)
#define PACK_EB  EDGE_COLS
#define PACK_TOTAL (PACK_W + PACK_B + PACK_EW + PACK_EB)

__global__ void k_pack(const float* __restrict__ q_w, const float* __restrict__ q_b,
                       const float* __restrict__ kv_w, const float* __restrict__ kv_b,
                       const float* __restrict__ qp_w, const float* __restrict__ qp_b,
                       const float* __restrict__ kvp_w, const float* __restrict__ kvp_b,
                       const float* __restrict__ b_w, const float* __restrict__ b_b,
                       const float* __restrict__ dz_w, const float* __restrict__ dz_b) {
    int gid = blockIdx.x * blockDim.x + threadIdx.x;
    if (gid < PACK_W) {
        int k = gid / PROJ_COLS, col = gid % PROJ_COLS;
        float v;
        if (col < 192)      v = q_w[k * 192 + col];
        else if (col < 576) v = kv_w[k * 384 + (col - 192)];
        else if (col < 720) v = qp_w[k * 144 + (col - 576)];
        else                v = kvp_w[k * 432 + (col - 720)];
        g_Wproj[gid] = v;
    } else if (gid < PACK_W + PACK_B) {
        int col = gid - PACK_W;
        float v;
        if (col < 192)      v = q_b[col];
        else if (col < 576) v = kv_b[col - 192];
        else if (col < 720) v = qp_b[col - 576];
        else                v = kvp_b[col - 720];
        g_Bproj[col] = v;
    } else if (gid < PACK_W + PACK_B + PACK_EW) {
        int idx = gid - PACK_W - PACK_B;
        int k = idx / EDGE_COLS, col = idx % EDGE_COLS;
        g_Wedge[idx] = (col < 12) ? b_w[k * 12 + col] : dz_w[k * 32 + (col - 12)];
    } else if (gid < PACK_TOTAL) {
        int col = gid - PACK_W - PACK_B - PACK_EW;
        g_Bedge[col] = (col < 12) ? b_b[col] : dz_b[col - 12];
    }
}

// ---------------- sorting: histogram / scan / scatter ----------------
__global__ void k_zero_hist() {
    int i = blockIdx.x * blockDim.x + threadIdx.x;
    if (i < NN) g_hist[i] = 0;
}
__global__ void k_hist(const int* __restrict__ edge_index) {
    int e = blockIdx.x * blockDim.x + threadIdx.x;
    if (e < NE) atomicAdd(&g_hist[edge_index[NE + e]], 1);
}
__global__ void k_scan() {
    __shared__ int partial[1024];
    int tid = threadIdx.x;
    int base = tid * 8;
    int local[8];
    int s = 0;
    #pragma unroll
    for (int i = 0; i < 8; i++) { local[i] = g_hist[base + i]; s += local[i]; }
    partial[tid] = s;
    __syncthreads();
    for (int d = 1; d < 1024; d <<= 1) {
        int v = 0;
        if (tid >= d) v = partial[tid - d];
        __syncthreads();
        if (tid >= d) partial[tid] += v;
        __syncthreads();
    }
    int run = partial[tid] - s;
    #pragma unroll
    for (int i = 0; i < 8; i++) {
        g_off[base + i] = run;
        g_cursor[base + i] = run;
        run += local[i];
    }
    if (tid == 1023) g_off[NN] = run;
}
__global__ void k_scatter(const int* __restrict__ edge_index) {
    int e = blockIdx.x * blockDim.x + threadIdx.x;
    if (e >= NE) return;
    int src = edge_index[NE + e];
    int dst = edge_index[e];
    int pos = atomicAdd(&g_cursor[src], 1);
    g_perm[pos] = e;
    g_nodeOf[pos] = src;
    g_dstOf[pos] = dst;
}

// ---------------- tf32 tensor-core GEMM (128x64 tile, BK=16, 8 warps) ----------------
__device__ __forceinline__ unsigned f2tf32(float x) {
    unsigned u;
    asm("cvt.rna.tf32.f32 %0, %1;" : "=r"(u) : "f"(x));
    return u;
}
__device__ __forceinline__ void mma_tf32(float* c, unsigned a0, unsigned a1, unsigned a2,
                                         unsigned a3, unsigned b0, unsigned b1) {
    asm volatile("mma.sync.aligned.m16n8k8.row.col.f32.tf32.tf32.f32 "
                 "{%0,%1,%2,%3}, {%4,%5,%6,%7}, {%8,%9}, {%0,%1,%2,%3};"
                 : "+f"(c[0]), "+f"(c[1]), "+f"(c[2]), "+f"(c[3])
                 : "r"(a0), "r"(a1), "r"(a2), "r"(a3), "r"(b0), "r"(b1));
}

#define AS_STR 130
#define BS_STR 72

template <int M, int N, int K>
__device__ __forceinline__ void mma_gemm_body(const float* __restrict__ A,
                                              const float* __restrict__ W,
                                              const float* __restrict__ Bias,
                                              float* __restrict__ C) {
    __shared__ unsigned As[16][AS_STR];
    __shared__ unsigned Bs[16][BS_STR];
    const int tid = threadIdx.x;
    const int lane = tid & 31, w = tid >> 5;
    const int gid = lane >> 2, tig = lane & 3;
    const int wm = (w & 3) * 32;
    const int wn = (w >> 2) * 32;
    const int row0 = blockIdx.y * 128, col0 = blockIdx.x * 64;

    float c[2][4][4];
    #pragma unroll
    for (int mt = 0; mt < 2; mt++)
        #pragma unroll
        for (int nt = 0; nt < 4; nt++)
            #pragma unroll
            for (int i = 0; i < 4; i++) c[mt][nt][i] = 0.f;

    for (int k0 = 0; k0 < K; k0 += 16) {
        // A tile: 128 rows x 16 k, float4 per load, coalesced
        #pragma unroll
        for (int l = 0; l < 2; l++) {
            int idx = tid + 256 * l;     // 0..511
            int r = idx >> 2;            // 0..127
            int kc = (idx & 3) * 4;
            float4 v = *reinterpret_cast<const float4*>(&A[(size_t)(row0 + r) * K + k0 + kc]);
            As[kc + 0][r] = f2tf32(v.x);
            As[kc + 1][r] = f2tf32(v.y);
            As[kc + 2][r] = f2tf32(v.z);
            As[kc + 3][r] = f2tf32(v.w);
        }
        // B tile: 16 rows x 64 cols
        if (N % 64 == 0) {
            int r = tid >> 4, c4 = (tid & 15) * 4;
            float4 v = *reinterpret_cast<const float4*>(&W[(size_t)(k0 + r) * N + col0 + c4]);
            Bs[r][c4 + 0] = f2tf32(v.x);
            Bs[r][c4 + 1] = f2tf32(v.y);
            Bs[r][c4 + 2] = f2tf32(v.z);
            Bs[r][c4 + 3] = f2tf32(v.w);
        } else {
            #pragma unroll
            for (int l = 0; l < 4; l++) {
                int idx = tid + 256 * l;
                int r = idx >> 6, cc = idx & 63;
                float v = 0.f;
                if (col0 + cc < N) v = W[(size_t)(k0 + r) * N + col0 + cc];
                Bs[r][cc] = f2tf32(v);
            }
        }
        __syncthreads();
        #pragma unroll
        for (int ks = 0; ks < 2; ks++) {
            int kb = ks * 8;
            unsigned a[2][4], b[4][2];
            #pragma unroll
            for (int mt = 0; mt < 2; mt++) {
                int m0 = wm + mt * 16;
                a[mt][0] = As[kb + tig][m0 + gid];
                a[mt][1] = As[kb + tig][m0 + gid + 8];
                a[mt][2] = As[kb + tig + 4][m0 + gid];
                a[mt][3] = As[kb + tig + 4][m0 + gid + 8];
            }
            #pragma unroll
            for (int nt = 0; nt < 4; nt++) {
                int n0 = wn + nt * 8;
                b[nt][0] = Bs[kb + tig][n0 + gid];
                b[nt][1] = Bs[kb + tig + 4][n0 + gid];
            }
            #pragma unroll
            for (int mt = 0; mt < 2; mt++)
                #pragma unroll
                for (int nt = 0; nt < 4; nt++)
                    mma_tf32(c[mt][nt], a[mt][0], a[mt][1], a[mt][2], a[mt][3],
                             b[nt][0], b[nt][1]);
        }
        __syncthreads();
    }
    // store
    #pragma unroll
    for (int mt = 0; mt < 2; mt++) {
        #pragma unroll
        for (int nt = 0; nt < 4; nt++) {
            int rbase = row0 + wm + mt * 16 + gid;
            int cbase = col0 + wn + nt * 8 + 2 * tig;
            #pragma unroll
            for (int i = 0; i < 2; i++) {
                int r = rbase + i * 8;
                #pragma unroll
                for (int j = 0; j < 2; j++) {
                    int cc = cbase + j;
                    if (cc < N) C[(size_t)r * N + cc] = c[mt][nt][i * 2 + j] + Bias[cc];
                }
            }
        }
    }
}

__global__ void k_gemm_proj(const float* __restrict__ s) {
    mma_gemm_body<NN, PROJ_COLS, CS>(s, g_Wproj, g_Bproj, g_proj);
}
__global__ void k_gemm_edge(const float* __restrict__ z) {
    mma_gemm_body<NE, EDGE_COLS, CZ>(z, g_Wedge, g_Bedge, g_bpz);
}
__global__ void k_gemm_out(const float* __restrict__ out_w, const float* __restrict__ out_b,
                           float* __restrict__ out) {
    mma_gemm_body<NN, CS, FEAT_COLS>(g_feats, out_w, out_b, out);
}

// ---------------- point transform ----------------
__global__ void k_pointify(const float* __restrict__ rot, const float* __restrict__ trans) {
    int gid = blockIdx.x * blockDim.x + threadIdx.x;
    if (gid >= NN * 192) return;
    int n = gid / 192;
    int p_all = gid % 192;
    const float* R = rot + (size_t)n * 9;
    const float* T = trans + (size_t)n * 3;
    const float* pr = g_proj + (size_t)n * PROJ_COLS;
    if (p_all < 48) {
        int p = p_all;
        float y0 = pr[576 + 0 * 48 + p];
        float y1 = pr[576 + 1 * 48 + p];
        float y2 = pr[576 + 2 * 48 + p];
        #pragma unroll
        for (int i = 0; i < 3; i++) {
            float v = R[i * 3 + 0] * y0 + R[i * 3 + 1] * y1 + R[i * 3 + 2] * y2 + T[i];
            g_qpts[((size_t)n * 48 + p) * 3 + i] = v;
        }
    } else {
        int p = p_all - 48;
        float y0 = pr[720 + 0 * 144 + p];
        float y1 = pr[720 + 1 * 144 + p];
        float y2 = pr[720 + 2 * 144 + p];
        int h = p / 12, j = p % 12;
        #pragma unroll
        for (int i = 0; i < 3; i++) {
            float v = R[i * 3 + 0] * y0 + R[i * 3 + 1] * y1 + R[i * 3 + 2] * y2 + T[i];
            if (j < PQK) g_kpts[((size_t)n * 48 + h * 4 + j) * 3 + i] = v;
            else         g_vpts[((size_t)n * 96 + h * 8 + (j - 4)) * 3 + i] = v;
        }
    }
}

// ---------------- per-(sorted-edge, head) attention logits ----------------
__global__ void k_logits(const float* __restrict__ mask, const float* __restrict__ head_weights) {
    int gid = blockIdx.x * blockDim.x + threadIdx.x;
    if (gid >= NE * HH) return;
    int t = gid / HH;
    int h = gid % HH;
    int n = g_nodeOf[t];
    int dst = g_dstOf[t];
    int e = g_perm[t];

    const float* qp = g_proj + (size_t)n * PROJ_COLS + h * 16;
    const float* kp = g_proj + (size_t)dst * PROJ_COLS + 192 + h * 32;
    float dot = 0.f;
    #pragma unroll
    for (int c = 0; c < CH; c++) dot += qp[c] * kp[c];

    float b = g_bpz[(size_t)e * EDGE_COLS + h];

    float pt = 0.f;
    const float* qq = g_qpts + ((size_t)n * 48 + h * 4) * 3;
    const float* kk = g_kpts + ((size_t)dst * 48 + h * 4) * 3;
    #pragma unroll
    for (int u = 0; u < PQK * 3; u++) {
        float d = qq[u] - kk[u];
        pt += d * d;
    }
    float hwv = log1pf(expf(head_weights[h])) * S_PT;
    float em = INF_C * (mask[dst] * mask[n] - 1.f);
    float a = dot * S_QK + S_B * b - 0.5f * hwv * pt + em;
    g_abuf[(size_t)t * HH + h] = a;
}

// ---------------- per-node softmax + aggregation + feature build ----------------
__global__ void k_node(const float* __restrict__ rot, const float* __restrict__ trans) {
    int n = blockIdx.x;
    int tid = threadIdx.x;
    int beg = g_off[n], end = g_off[n + 1];
    int dn = end - beg;

    __shared__ float sred[192];
    __shared__ float s_amax[HH], s_inv[HH];
    __shared__ float wch[64 * HH];
    __shared__ int dsh[64], esh[64];
    __shared__ float sacc[864];

    if (tid < 192) {
        int h = tid % HH, j = tid / HH;
        float m = -INFINITY;
        for (int i = j; i < dn; i += 16) m = fmaxf(m, g_abuf[(size_t)(beg + i) * HH + h]);
        sred[tid] = m;
    }
    __syncthreads();
    if (tid < HH) {
        float m = -INFINITY;
        #pragma unroll
        for (int j = 0; j < 16; j++) m = fmaxf(m, sred[j * HH + tid]);
        if (!isfinite(m)) m = 0.f;
        s_amax[tid] = m;
    }
    __syncthreads();
    if (tid < 192) {
        int h = tid % HH, j = tid / HH;
        float am = s_amax[h];
        float s = 0.f;
        for (int i = j; i < dn; i += 16) s += expf(g_abuf[(size_t)(beg + i) * HH + h] - am);
        sred[tid] = s;
    }
    __syncthreads();
    if (tid < HH) {
        float s = 0.f;
        #pragma unroll
        for (int j = 0; j < 16; j++) s += sred[j * HH + tid];
        s_inv[tid] = 1.f / (s + 1e-16f);
    }
    __syncthreads();

    float acc[4] = {0.f, 0.f, 0.f, 0.f};
    int typ[4], hsel[4], coff[4];
    #pragma unroll
    for (int k = 0; k < 4; k++) {
        int c = tid + 256 * k;
        if (c < 192) {
            typ[k] = 0; hsel[k] = c / 16;
            coff[k] = 192 + (c / 16) * 32 + 16 + (c % 16);
        } else if (c < 480) {
            int u = c - 192;
            typ[k] = 1; hsel[k] = u / 24; coff[k] = u;
        } else if (c < 864) {
            int u = c - 480;
            typ[k] = 2; hsel[k] = u / 32; coff[k] = 12 + (u % 32);
        } else { typ[k] = 3; hsel[k] = 0; coff[k] = 0; }
    }

    for (int c0 = 0; c0 < dn; c0 += 64) {
        int cn = min(64, dn - c0);
        __syncthreads();
        for (int t = tid; t < cn * HH; t += 256) {
            int i = t / HH, h = t % HH;
            wch[t] = expf(g_abuf[(size_t)(beg + c0 + i) * HH + h] - s_amax[h]) * s_inv[h];
        }
        if (tid < cn) {
            dsh[tid] = g_dstOf[beg + c0 + tid];
            esh[tid] = g_perm[beg + c0 + tid];
        }
        __syncthreads();
        for (int i = 0; i < cn; i++) {
            int dst = dsh[i];
            int e = esh[i];
            #pragma unroll
            for (int k = 0; k < 4; k++) {
                if (typ[k] == 3) continue;
                float v;
                if (typ[k] == 0)      v = g_proj[(size_t)dst * PROJ_COLS + coff[k]];
                else if (typ[k] == 1) v = g_vpts[(size_t)dst * 288 + coff[k]];
                else                  v = g_bpz[(size_t)e * EDGE_COLS + coff[k]];
                acc[k] += wch[i * HH + hsel[k]] * v;
            }
        }
    }

    #pragma unroll
    for (int k = 0; k < 4; k++) {
        int c = tid + 256 * k;
        if (c < 864) sacc[c] = acc[k];
    }
    __syncthreads();

    float* f = g_feats + (size_t)n * FEAT_COLS;
    if (tid < 192) f[tid] = sacc[tid];
    for (int t = tid; t < 384; t += 256) f[576 + t] = sacc[480 + t];
    if (tid < 96) {
        int q = tid;
        float g0 = sacc[192 + q * 3 + 0] - trans[(size_t)n * 3 + 0];
        float g1 = sacc[192 + q * 3 + 1] - trans[(size_t)n * 3 + 1];
        float g2 = sacc[192 + q * 3 + 2] - trans[(size_t)n * 3 + 2];
        const float* R = rot + (size_t)n * 9;
        float l0 = R[0] * g0 + R[3] * g1 + R[6] * g2;
        float l1 = R[1] * g0 + R[4] * g1 + R[7] * g2;
        float l2 = R[2] * g0 + R[5] * g1 + R[8] * g2;
        f[192 + q] = l0;
        f[288 + q] = l1;
        f[384 + q] = l2;
        f[480 + q] = sqrtf(l0 * l0 + l1 * l1 + l2 * l2 + 1e-8f);
    }
}

// ---------------- launch ----------------
extern "C" void kernel_launch(void* const* d_in, const int* in_sizes, int n_in,
                              void* d_out, int out_size) {
    const float* s          = (const float*)d_in[0];
    const float* z          = (const float*)d_in[1];
    const int*   edge_index = (const int*)  d_in[2];
    const float* rot        = (const float*)d_in[3];
    const float* trans      = (const float*)d_in[4];
    const float* mask       = (const float*)d_in[5];
    const float* q_w        = (const float*)d_in[6];
    const float* q_b        = (const float*)d_in[7];
    const float* kv_w       = (const float*)d_in[8];
    const float* kv_b       = (const float*)d_in[9];
    const float* qp_w       = (const float*)d_in[10];
    const float* qp_b       = (const float*)d_in[11];
    const float* kvp_w      = (const float*)d_in[12];
    const float* kvp_b      = (const float*)d_in[13];
    const float* b_w        = (const float*)d_in[14];
    const float* b_b        = (const float*)d_in[15];
    const float* dz_w       = (const float*)d_in[16];
    const float* dz_b       = (const float*)d_in[17];
    const float* head_w     = (const float*)d_in[18];
    const float* out_w      = (const float*)d_in[19];
    const float* out_b      = (const float*)d_in[20];
    float* out = (float*)d_out;

    k_pack<<<(PACK_TOTAL + 255) / 256, 256>>>(q_w, q_b, kv_w, kv_b, qp_w, qp_b,
                                              kvp_w, kvp_b, b_w, b_b, dz_w, dz_b);
    k_zero_hist<<<NN / 256, 256>>>();
    k_hist<<<NE / 256, 256>>>(edge_index);
    k_scan<<<1, 1024>>>();
    k_scatter<<<NE / 256, 256>>>(edge_index);

    k_gemm_proj<<<dim3(PROJ_COLS / 64, NN / 128), 256>>>(s);
    k_pointify<<<(NN * 192) / 256, 256>>>(rot, trans);
    k_gemm_edge<<<dim3(1, NE / 128), 256>>>(z);
    k_logits<<<(NE * HH) / 256, 256>>>(mask, head_w);
    k_node<<<NN, 256>>>(rot, trans);
    k_gemm_out<<<dim3(CS / 64, NN / 128), 256>>>(out_w, out_b, out);
}

// round 3
// speedup vs baseline: 1.8948x; 1.5379x over previous
#include <cuda_runtime.h>
#include <math.h>

#define NN 8192
#define NE 262144
#define CS 384
#define CZ 128
#define CH 16
#define HH 12
#define PQK 4
#define PV 8
#define PROJ_COLS 1152      // 192 q | 384 kv | 144 qp | 432 kvp
#define EDGE_COLS 44        // 12 b | 32 pz
#define BPZ_LD 48           // padded row stride for sorted b/pz
#define FEAT_COLS 960
#define S_QK 0.14433756729740643f
#define S_B  0.5773502691896258f
#define S_PT 0.1360827634879543f
#define INF_C 100000.0f
#define DN_FAST 128

// ---------------- scratch ----------------
__device__ float g_proj[(size_t)NN * PROJ_COLS];
__device__ float g_qpts[(size_t)NN * HH * PQK * 3];   // 144/node
__device__ float g_kpts[(size_t)NN * HH * PQK * 3];   // 144/node
__device__ float g_vpts[(size_t)NN * HH * PV * 3];    // 288/node
__device__ float g_bpzs[(size_t)NE * BPZ_LD];         // sorted by src
__device__ float g_abuf[(size_t)NE * HH];             // slow-path only
__device__ float g_feats[(size_t)NN * FEAT_COLS];
__device__ int   g_rank[NE];
__device__ int   g_dstOf[NE];
__device__ int   g_hist[NN];
__device__ int   g_off[NN + 1];
__device__ int   g_cursor[NN];
__device__ float g_Wproj[CS * PROJ_COLS];
__device__ float g_Bproj[PROJ_COLS];
__device__ float g_Wedge[CZ * EDGE_COLS];
__device__ float g_Bedge[EDGE_COLS];

// ---------------- weight packing ----------------
#define PACK_W   (CS * PROJ_COLS)
#define PACK_B   PROJ_COLS
#define PACK_EW  (CZ * EDGE_COLS)
#define PACK_EB  EDGE_COLS
#define PACK_TOTAL (PACK_W + PACK_B + PACK_EW + PACK_EB)

__global__ void k_pack(const float* __restrict__ q_w, const float* __restrict__ q_b,
                       const float* __restrict__ kv_w, const float* __restrict__ kv_b,
                       const float* __restrict__ qp_w, const float* __restrict__ qp_b,
                       const float* __restrict__ kvp_w, const float* __restrict__ kvp_b,
                       const float* __restrict__ b_w, const float* __restrict__ b_b,
                       const float* __restrict__ dz_w, const float* __restrict__ dz_b) {
    int gid = blockIdx.x * blockDim.x + threadIdx.x;
    if (gid < PACK_W) {
        int k = gid / PROJ_COLS, col = gid % PROJ_COLS;
        float v;
        if (col < 192)      v = q_w[k * 192 + col];
        else if (col < 576) v = kv_w[k * 384 + (col - 192)];
        else if (col < 720) v = qp_w[k * 144 + (col - 576)];
        else                v = kvp_w[k * 432 + (col - 720)];
        g_Wproj[gid] = v;
    } else if (gid < PACK_W + PACK_B) {
        int col = gid - PACK_W;
        float v;
        if (col < 192)      v = q_b[col];
        else if (col < 576) v = kv_b[col - 192];
        else if (col < 720) v = qp_b[col - 576];
        else                v = kvp_b[col - 720];
        g_Bproj[col] = v;
    } else if (gid < PACK_W + PACK_B + PACK_EW) {
        int idx = gid - PACK_W - PACK_B;
        int k = idx / EDGE_COLS, col = idx % EDGE_COLS;
        g_Wedge[idx] = (col < 12) ? b_w[k * 12 + col] : dz_w[k * 32 + (col - 12)];
    } else if (gid < PACK_TOTAL) {
        int col = gid - PACK_W - PACK_B - PACK_EW;
        g_Bedge[col] = (col < 12) ? b_b[col] : dz_b[col - 12];
    }
}

// ---------------- sorting ----------------
__global__ void k_zero_hist() {
    int i = blockIdx.x * blockDim.x + threadIdx.x;
    if (i < NN) g_hist[i] = 0;
}
__global__ void k_hist(const int* __restrict__ edge_index) {
    int e = blockIdx.x * blockDim.x + threadIdx.x;
    if (e < NE) atomicAdd(&g_hist[edge_index[NE + e]], 1);
}
__global__ void k_scan() {
    __shared__ int partial[1024];
    int tid = threadIdx.x;
    int base = tid * 8;
    int local[8];
    int s = 0;
    #pragma unroll
    for (int i = 0; i < 8; i++) { local[i] = g_hist[base + i]; s += local[i]; }
    partial[tid] = s;
    __syncthreads();
    for (int d = 1; d < 1024; d <<= 1) {
        int v = 0;
        if (tid >= d) v = partial[tid - d];
        __syncthreads();
        if (tid >= d) partial[tid] += v;
        __syncthreads();
    }
    int run = partial[tid] - s;
    #pragma unroll
    for (int i = 0; i < 8; i++) {
        g_off[base + i] = run;
        g_cursor[base + i] = run;
        run += local[i];
    }
    if (tid == 1023) g_off[NN] = run;
}
__global__ void k_scatter(const int* __restrict__ edge_index) {
    int e = blockIdx.x * blockDim.x + threadIdx.x;
    if (e >= NE) return;
    int src = edge_index[NE + e];
    int dst = edge_index[e];
    int pos = atomicAdd(&g_cursor[src], 1);
    g_rank[e] = pos;
    g_dstOf[pos] = dst;
}

// ---------------- tf32 tensor-core GEMM ----------------
__device__ __forceinline__ unsigned f2tf32(float x) {
    unsigned u;
    asm("cvt.rna.tf32.f32 %0, %1;" : "=r"(u) : "f"(x));
    return u;
}
__device__ __forceinline__ void mma_tf32(float* c, unsigned a0, unsigned a1, unsigned a2,
                                         unsigned a3, unsigned b0, unsigned b1) {
    asm volatile("mma.sync.aligned.m16n8k8.row.col.f32.tf32.tf32.f32 "
                 "{%0,%1,%2,%3}, {%4,%5,%6,%7}, {%8,%9}, {%0,%1,%2,%3};"
                 : "+f"(c[0]), "+f"(c[1]), "+f"(c[2]), "+f"(c[3])
                 : "r"(a0), "r"(a1), "r"(a2), "r"(a3), "r"(b0), "r"(b1));
}

#define AS_STR 130
#define BS_STR 72

template <int M, int N, int K, int LDC, bool REMAP>
__device__ __forceinline__ void mma_gemm_body(const float* __restrict__ A,
                                              const float* __restrict__ W,
                                              const float* __restrict__ Bias,
                                              float* __restrict__ C,
                                              const int* __restrict__ rowmap) {
    __shared__ unsigned As[16][AS_STR];
    __shared__ unsigned Bs[16][BS_STR];
    const int tid = threadIdx.x;
    const int lane = tid & 31, w = tid >> 5;
    const int gid = lane >> 2, tig = lane & 3;
    const int wm = (w & 3) * 32;
    const int wn = (w >> 2) * 32;
    const int row0 = blockIdx.y * 128, col0 = blockIdx.x * 64;

    float c[2][4][4];
    #pragma unroll
    for (int mt = 0; mt < 2; mt++)
        #pragma unroll
        for (int nt = 0; nt < 4; nt++)
            #pragma unroll
            for (int i = 0; i < 4; i++) c[mt][nt][i] = 0.f;

    for (int k0 = 0; k0 < K; k0 += 16) {
        #pragma unroll
        for (int l = 0; l < 2; l++) {
            int idx = tid + 256 * l;
            int r = idx >> 2;
            int kc = (idx & 3) * 4;
            float4 v = *reinterpret_cast<const float4*>(&A[(size_t)(row0 + r) * K + k0 + kc]);
            As[kc + 0][r] = f2tf32(v.x);
            As[kc + 1][r] = f2tf32(v.y);
            As[kc + 2][r] = f2tf32(v.z);
            As[kc + 3][r] = f2tf32(v.w);
        }
        if (N % 64 == 0) {
            int r = tid >> 4, c4 = (tid & 15) * 4;
            float4 v = *reinterpret_cast<const float4*>(&W[(size_t)(k0 + r) * N + col0 + c4]);
            Bs[r][c4 + 0] = f2tf32(v.x);
            Bs[r][c4 + 1] = f2tf32(v.y);
            Bs[r][c4 + 2] = f2tf32(v.z);
            Bs[r][c4 + 3] = f2tf32(v.w);
        } else {
            #pragma unroll
            for (int l = 0; l < 4; l++) {
                int idx = tid + 256 * l;
                int r = idx >> 6, cc = idx & 63;
                float v = 0.f;
                if (col0 + cc < N) v = W[(size_t)(k0 + r) * N + col0 + cc];
                Bs[r][cc] = f2tf32(v);
            }
        }
        __syncthreads();
        #pragma unroll
        for (int ks = 0; ks < 2; ks++) {
            int kb = ks * 8;
            unsigned a[2][4], b[4][2];
            #pragma unroll
            for (int mt = 0; mt < 2; mt++) {
                int m0 = wm + mt * 16;
                a[mt][0] = As[kb + tig][m0 + gid];
                a[mt][1] = As[kb + tig][m0 + gid + 8];
                a[mt][2] = As[kb + tig + 4][m0 + gid];
                a[mt][3] = As[kb + tig + 4][m0 + gid + 8];
            }
            #pragma unroll
            for (int nt = 0; nt < 4; nt++) {
                int n0 = wn + nt * 8;
                b[nt][0] = Bs[kb + tig][n0 + gid];
                b[nt][1] = Bs[kb + tig + 4][n0 + gid];
            }
            #pragma unroll
            for (int mt = 0; mt < 2; mt++)
                #pragma unroll
                for (int nt = 0; nt < 4; nt++)
                    mma_tf32(c[mt][nt], a[mt][0], a[mt][1], a[mt][2], a[mt][3],
                             b[nt][0], b[nt][1]);
        }
        __syncthreads();
    }
    #pragma unroll
    for (int mt = 0; mt < 2; mt++) {
        #pragma unroll
        for (int i = 0; i < 2; i++) {
            int r = row0 + wm + mt * 16 + gid + i * 8;
            int crow = REMAP ? rowmap[r] : r;
            #pragma unroll
            for (int nt = 0; nt < 4; nt++) {
                int cbase = col0 + wn + nt * 8 + 2 * tig;
                #pragma unroll
                for (int j = 0; j < 2; j++) {
                    int cc = cbase + j;
                    if (cc < N) C[(size_t)crow * LDC + cc] = c[mt][nt][i * 2 + j] + Bias[cc];
                }
            }
        }
    }
}

__global__ void k_gemm_proj(const float* __restrict__ s) {
    mma_gemm_body<NN, PROJ_COLS, CS, PROJ_COLS, false>(s, g_Wproj, g_Bproj, g_proj, nullptr);
}
__global__ void k_gemm_edge(const float* __restrict__ z) {
    mma_gemm_body<NE, EDGE_COLS, CZ, BPZ_LD, true>(z, g_Wedge, g_Bedge, g_bpzs, g_rank);
}
__global__ void k_gemm_out(const float* __restrict__ out_w, const float* __restrict__ out_b,
                           float* __restrict__ out) {
    mma_gemm_body<NN, CS, FEAT_COLS, CS, false>(g_feats, out_w, out_b, out, nullptr);
}

// ---------------- point transform ----------------
__global__ void k_pointify(const float* __restrict__ rot, const float* __restrict__ trans) {
    int gid = blockIdx.x * blockDim.x + threadIdx.x;
    if (gid >= NN * 192) return;
    int n = gid / 192;
    int p_all = gid % 192;
    const float* R = rot + (size_t)n * 9;
    const float* T = trans + (size_t)n * 3;
    const float* pr = g_proj + (size_t)n * PROJ_COLS;
    if (p_all < 48) {
        int p = p_all;
        float y0 = pr[576 + 0 * 48 + p];
        float y1 = pr[576 + 1 * 48 + p];
        float y2 = pr[576 + 2 * 48 + p];
        #pragma unroll
        for (int i = 0; i < 3; i++) {
            float v = R[i * 3 + 0] * y0 + R[i * 3 + 1] * y1 + R[i * 3 + 2] * y2 + T[i];
            g_qpts[((size_t)n * 48 + p) * 3 + i] = v;
        }
    } else {
        int p = p_all - 48;
        float y0 = pr[720 + 0 * 144 + p];
        float y1 = pr[720 + 1 * 144 + p];
        float y2 = pr[720 + 2 * 144 + p];
        int h = p / 12, j = p % 12;
        #pragma unroll
        for (int i = 0; i < 3; i++) {
            float v = R[i * 3 + 0] * y0 + R[i * 3 + 1] * y1 + R[i * 3 + 2] * y2 + T[i];
            if (j < PQK) g_kpts[((size_t)n * 48 + h * 4 + j) * 3 + i] = v;
            else         g_vpts[((size_t)n * 96 + h * 8 + (j - 4)) * 3 + i] = v;
        }
    }
}

// ---------------- fused per-node: logits + softmax + aggregation ----------------
__device__ __forceinline__ float dot4(float4 a, float4 b) {
    return a.x * b.x + a.y * b.y + a.z * b.z + a.w * b.w;
}

template <bool FAST>
__device__ __forceinline__ void node_body(
    int n, int tid, int beg, int dn,
    const float* __restrict__ mask, const float* __restrict__ head_weights,
    const float* __restrict__ rot, const float* __restrict__ trans,
    float4* s_q, float4* s_qp, float* s_hw, float* s_logit, int* s_dst,
    float* s_red, float* s_amax, float* s_inv, float* sacc) {

    const float4* proj4 = reinterpret_cast<const float4*>(g_proj);
    const float4* kpts4 = reinterpret_cast<const float4*>(g_kpts);
    const float4* vpts4 = reinterpret_cast<const float4*>(g_vpts);
    const float4* bpzs4 = reinterpret_cast<const float4*>(g_bpzs);

    float* lb = FAST ? s_logit : (g_abuf + (size_t)beg * HH);
    const int* dl = FAST ? s_dst : (g_dstOf + beg);

    // Phase A: stage node-side data
    if (tid < 48) s_q[tid] = proj4[(size_t)n * 288 + tid];
    else if (tid < 84) s_qp[tid - 48] = kpts4[0] , s_qp[tid - 48] = reinterpret_cast<const float4*>(g_qpts)[(size_t)n * 36 + (tid - 48)];
    else if (tid < 96) s_hw[tid - 84] = 0.5f * S_PT * log1pf(expf(head_weights[tid - 84]));
    if (FAST) {
        for (int i = tid; i < dn; i += 256) s_dst[i] = g_dstOf[beg + i];
    }
    __syncthreads();

    float mn = mask[n];

    // Phase B: logits
    if (tid < 252) {
        int h = tid % HH;
        float4 q0 = s_q[h * 4 + 0], q1 = s_q[h * 4 + 1], q2 = s_q[h * 4 + 2], q3 = s_q[h * 4 + 3];
        float4 p0 = s_qp[h * 3 + 0], p1 = s_qp[h * 3 + 1], p2 = s_qp[h * 3 + 2];
        float hwv = s_hw[h];
        for (int i = tid / HH; i < dn; i += 21) {
            int dst = dl[i];
            const float4* kr = proj4 + (size_t)dst * 288 + 48 + h * 8;
            float dot = dot4(q0, kr[0]) + dot4(q1, kr[1]) + dot4(q2, kr[2]) + dot4(q3, kr[3]);
            const float4* kp = kpts4 + (size_t)dst * 36 + h * 3;
            float4 d0 = kp[0], d1 = kp[1], d2 = kp[2];
            float pt = 0.f;
            pt += (p0.x - d0.x) * (p0.x - d0.x) + (p0.y - d0.y) * (p0.y - d0.y)
                + (p0.z - d0.z) * (p0.z - d0.z) + (p0.w - d0.w) * (p0.w - d0.w);
            pt += (p1.x - d1.x) * (p1.x - d1.x) + (p1.y - d1.y) * (p1.y - d1.y)
                + (p1.z - d1.z) * (p1.z - d1.z) + (p1.w - d1.w) * (p1.w - d1.w);
            pt += (p2.x - d2.x) * (p2.x - d2.x) + (p2.y - d2.y) * (p2.y - d2.y)
                + (p2.z - d2.z) * (p2.z - d2.z) + (p2.w - d2.w) * (p2.w - d2.w);
            float b = g_bpzs[(size_t)(beg + i) * BPZ_LD + h];
            float em = INF_C * (mask[dst] * mn - 1.f);
            lb[i * HH + h] = dot * S_QK + S_B * b - hwv * pt + em;
        }
    }
    __syncthreads();

    // Phase C: per-head max and denom
    if (tid < 96) {
        int h = tid % HH, j = tid / HH;
        float m = -INFINITY;
        for (int i = j; i < dn; i += 8) m = fmaxf(m, lb[i * HH + h]);
        s_red[tid] = m;
    }
    __syncthreads();
    if (tid < HH) {
        float m = -INFINITY;
        #pragma unroll
        for (int j = 0; j < 8; j++) m = fmaxf(m, s_red[j * HH + tid]);
        if (!isfinite(m)) m = 0.f;
        s_amax[tid] = m;
    }
    __syncthreads();
    if (tid < 96) {
        int h = tid % HH, j = tid / HH;
        float am = s_amax[h];
        float s = 0.f;
        for (int i = j; i < dn; i += 8) s += expf(lb[i * HH + h] - am);
        s_red[tid] = s;
    }
    __syncthreads();
    if (tid < HH) {
        float s = 0.f;
        #pragma unroll
        for (int j = 0; j < 8; j++) s += s_red[j * HH + tid];
        s_inv[tid] = 1.f / (s + 1e-16f);
    }
    __syncthreads();

    // Phase D: logits -> normalized weights (in place)
    for (int idx = tid; idx < dn * HH; idx += 256) {
        int h = idx % HH;
        lb[idx] = expf(lb[idx] - s_amax[h]) * s_inv[h];
    }
    __syncthreads();

    // Phase E: aggregation (warp-aligned groups)
    if (tid < 48) {                       // o: 48 float4
        int h = tid >> 2, c4 = tid & 3;
        float4 acc = {0.f, 0.f, 0.f, 0.f};
        for (int i = 0; i < dn; i++) {
            int dst = dl[i];
            float w = lb[i * HH + h];
            float4 v = proj4[(size_t)dst * 288 + 48 + h * 8 + 4 + c4];
            acc.x += w * v.x; acc.y += w * v.y; acc.z += w * v.z; acc.w += w * v.w;
        }
        sacc[tid * 4 + 0] = acc.x; sacc[tid * 4 + 1] = acc.y;
        sacc[tid * 4 + 2] = acc.z; sacc[tid * 4 + 3] = acc.w;
    } else if (tid >= 64 && tid < 136) {  // o_pt: 72 float4
        int c = tid - 64;
        int h = c / 6;
        float4 acc = {0.f, 0.f, 0.f, 0.f};
        for (int i = 0; i < dn; i++) {
            int dst = dl[i];
            float w = lb[i * HH + h];
            float4 v = vpts4[(size_t)dst * 72 + c];
            acc.x += w * v.x; acc.y += w * v.y; acc.z += w * v.z; acc.w += w * v.w;
        }
        sacc[192 + c * 4 + 0] = acc.x; sacc[192 + c * 4 + 1] = acc.y;
        sacc[192 + c * 4 + 2] = acc.z; sacc[192 + c * 4 + 3] = acc.w;
    } else if (tid >= 160 && tid < 184) { // o_pair: 24 threads x 4 heads
        int c = tid - 160;
        int j = c & 7, hq = c >> 3;
        float4 acc[4];
        #pragma unroll
        for (int r = 0; r < 4; r++) acc[r] = make_float4(0.f, 0.f, 0.f, 0.f);
        for (int i = 0; i < dn; i++) {
            float4 p = bpzs4[(size_t)(beg + i) * 12 + 3 + j];
            #pragma unroll
            for (int r = 0; r < 4; r++) {
                float w = lb[i * HH + hq * 4 + r];
                acc[r].x += w * p.x; acc[r].y += w * p.y;
                acc[r].z += w * p.z; acc[r].w += w * p.w;
            }
        }
        #pragma unroll
        for (int r = 0; r < 4; r++) {
            int base = 480 + (hq * 4 + r) * 32 + j * 4;
            sacc[base + 0] = acc[r].x; sacc[base + 1] = acc[r].y;
            sacc[base + 2] = acc[r].z; sacc[base + 3] = acc[r].w;
        }
    }
    __syncthreads();

    // Phase F: finalize features
    float* f = g_feats + (size_t)n * FEAT_COLS;
    if (tid < 192) f[tid] = sacc[tid];
    for (int t = tid; t < 384; t += 256) f[576 + t] = sacc[480 + t];
    if (tid < 96) {
        int q = tid;
        float g0 = sacc[192 + q * 3 + 0] - trans[(size_t)n * 3 + 0];
        float g1 = sacc[192 + q * 3 + 1] - trans[(size_t)n * 3 + 1];
        float g2 = sacc[192 + q * 3 + 2] - trans[(size_t)n * 3 + 2];
        const float* R = rot + (size_t)n * 9;
        float l0 = R[0] * g0 + R[3] * g1 + R[6] * g2;
        float l1 = R[1] * g0 + R[4] * g1 + R[7] * g2;
        float l2 = R[2] * g0 + R[5] * g1 + R[8] * g2;
        f[192 + q] = l0;
        f[288 + q] = l1;
        f[384 + q] = l2;
        f[480 + q] = sqrtf(l0 * l0 + l1 * l1 + l2 * l2 + 1e-8f);
    }
}

__global__ void k_node(const float* __restrict__ mask, const float* __restrict__ head_weights,
                       const float* __restrict__ rot, const float* __restrict__ trans) {
    __shared__ float4 s_q[48];
    __shared__ float4 s_qp[36];
    __shared__ float  s_hw[12];
    __shared__ float  s_logit[DN_FAST * HH];
    __shared__ int    s_dst[DN_FAST];
    __shared__ float  s_red[96];
    __shared__ float  s_amax[HH], s_inv[HH];
    __shared__ float  sacc[864];

    int n = blockIdx.x;
    int tid = threadIdx.x;
    int beg = g_off[n], dn = g_off[n + 1] - beg;

    if (dn <= DN_FAST)
        node_body<true>(n, tid, beg, dn, mask, head_weights, rot, trans,
                        s_q, s_qp, s_hw, s_logit, s_dst, s_red, s_amax, s_inv, sacc);
    else
        node_body<false>(n, tid, beg, dn, mask, head_weights, rot, trans,
                         s_q, s_qp, s_hw, s_logit, s_dst, s_red, s_amax, s_inv, sacc);
}

// ---------------- launch ----------------
extern "C" void kernel_launch(void* const* d_in, const int* in_sizes, int n_in,
                              void* d_out, int out_size) {
    const float* s          = (const float*)d_in[0];
    const float* z          = (const float*)d_in[1];
    const int*   edge_index = (const int*)  d_in[2];
    const float* rot        = (const float*)d_in[3];
    const float* trans      = (const float*)d_in[4];
    const float* mask       = (const float*)d_in[5];
    const float* q_w        = (const float*)d_in[6];
    const float* q_b        = (const float*)d_in[7];
    const float* kv_w       = (const float*)d_in[8];
    const float* kv_b       = (const float*)d_in[9];
    const float* qp_w       = (const float*)d_in[10];
    const float* qp_b       = (const float*)d_in[11];
    const float* kvp_w      = (const float*)d_in[12];
    const float* kvp_b      = (const float*)d_in[13];
    const float* b_w        = (const float*)d_in[14];
    const float* b_b        = (const float*)d_in[15];
    const float* dz_w       = (const float*)d_in[16];
    const float* dz_b       = (const float*)d_in[17];
    const float* head_w     = (const float*)d_in[18];
    const float* out_w      = (const float*)d_in[19];
    const float* out_b      = (const float*)d_in[20];
    float* out = (float*)d_out;

    k_pack<<<(PACK_TOTAL + 255) / 256, 256>>>(q_w, q_b, kv_w, kv_b, qp_w, qp_b,
                                              kvp_w, kvp_b, b_w, b_b, dz_w, dz_b);
    k_zero_hist<<<NN / 256, 256>>>();
    k_hist<<<NE / 256, 256>>>(edge_index);
    k_scan<<<1, 1024>>>();
    k_scatter<<<NE / 256, 256>>>(edge_index);

    k_gemm_proj<<<dim3(PROJ_COLS / 64, NN / 128), 256>>>(s);
    k_pointify<<<(NN * 192) / 256, 256>>>(rot, trans);
    k_gemm_edge<<<dim3(1, NE / 128), 256>>>(z);
    k_node<<<NN, 256>>>(mask, head_w, rot, trans);
    k_gemm_out<<<dim3(CS / 64, NN / 128), 256>>>(out_w, out_b, out);
}

// round 4
// speedup vs baseline: 2.1326x; 1.1255x over previous
#include <cuda_runtime.h>
#include <math.h>

#define NN 8192
#define NE 262144
#define CS 384
#define CZ 128
#define CH 16
#define HH 12
#define PQK 4
#define PV 8
#define PROJ_COLS 1152      // 192 q | 384 kv | 144 qp | 432 kvp
#define EDGE_COLS 44        // 12 b | 32 pz
#define BPZ_LD 48           // padded row stride for sorted b/pz
#define FEAT_COLS 960
#define S_QK 0.14433756729740643f
#define S_B  0.5773502691896258f
#define S_PT 0.1360827634879543f
#define INF_C 100000.0f
#define DN_FAST 128

// ---------------- scratch ----------------
__device__ float g_proj[(size_t)NN * PROJ_COLS];
__device__ float g_qpts[(size_t)NN * HH * PQK * 3];
__device__ float g_kpts[(size_t)NN * HH * PQK * 3];
__device__ float g_vpts[(size_t)NN * HH * PV * 3];
__device__ float g_bpzs[(size_t)NE * BPZ_LD];
__device__ float g_abuf[(size_t)NE * HH];
__device__ float g_feats[(size_t)NN * FEAT_COLS];
__device__ int   g_rank[NE];
__device__ int   g_dstOf[NE];
__device__ int   g_hist[NN];
__device__ int   g_off[NN + 1];
__device__ int   g_cursor[NN];
__device__ float g_Wproj[CS * PROJ_COLS];
__device__ float g_Bproj[PROJ_COLS];
__device__ float g_Wedge[CZ * EDGE_COLS];
__device__ float g_Bedge[EDGE_COLS];

// ---------------- weight packing ----------------
#define PACK_W   (CS * PROJ_COLS)
#define PACK_B   PROJ_COLS
#define PACK_EW  (CZ * EDGE_COLS)
#define PACK_EB  EDGE_COLS
#define PACK_TOTAL (PACK_W + PACK_B + PACK_EW + PACK_EB)

__global__ void k_pack(const float* __restrict__ q_w, const float* __restrict__ q_b,
                       const float* __restrict__ kv_w, const float* __restrict__ kv_b,
                       const float* __restrict__ qp_w, const float* __restrict__ qp_b,
                       const float* __restrict__ kvp_w, const float* __restrict__ kvp_b,
                       const float* __restrict__ b_w, const float* __restrict__ b_b,
                       const float* __restrict__ dz_w, const float* __restrict__ dz_b) {
    int gid = blockIdx.x * blockDim.x + threadIdx.x;
    if (gid < PACK_W) {
        int k = gid / PROJ_COLS, col = gid % PROJ_COLS;
        float v;
        if (col < 192)      v = q_w[k * 192 + col];
        else if (col < 576) v = kv_w[k * 384 + (col - 192)];
        else if (col < 720) v = qp_w[k * 144 + (col - 576)];
        else                v = kvp_w[k * 432 + (col - 720)];
        g_Wproj[gid] = v;
    } else if (gid < PACK_W + PACK_B) {
        int col = gid - PACK_W;
        float v;
        if (col < 192)      v = q_b[col];
        else if (col < 576) v = kv_b[col - 192];
        else if (col < 720) v = qp_b[col - 576];
        else                v = kvp_b[col - 720];
        g_Bproj[col] = v;
    } else if (gid < PACK_W + PACK_B + PACK_EW) {
        int idx = gid - PACK_W - PACK_B;
        int k = idx / EDGE_COLS, col = idx % EDGE_COLS;
        g_Wedge[idx] = (col < 12) ? b_w[k * 12 + col] : dz_w[k * 32 + (col - 12)];
    } else if (gid < PACK_TOTAL) {
        int col = gid - PACK_W - PACK_B - PACK_EW;
        g_Bedge[col] = (col < 12) ? b_b[col] : dz_b[col - 12];
    }
}

// ---------------- sorting ----------------
__global__ void k_zero_hist() {
    int i = blockIdx.x * blockDim.x + threadIdx.x;
    if (i < NN) g_hist[i] = 0;
}
__global__ void k_hist(const int* __restrict__ edge_index) {
    int e = blockIdx.x * blockDim.x + threadIdx.x;
    if (e < NE) atomicAdd(&g_hist[edge_index[NE + e]], 1);
}
__global__ void k_scan() {
    __shared__ int partial[1024];
    int tid = threadIdx.x;
    int base = tid * 8;
    int local[8];
    int s = 0;
    #pragma unroll
    for (int i = 0; i < 8; i++) { local[i] = g_hist[base + i]; s += local[i]; }
    partial[tid] = s;
    __syncthreads();
    for (int d = 1; d < 1024; d <<= 1) {
        int v = 0;
        if (tid >= d) v = partial[tid - d];
        __syncthreads();
        if (tid >= d) partial[tid] += v;
        __syncthreads();
    }
    int run = partial[tid] - s;
    #pragma unroll
    for (int i = 0; i < 8; i++) {
        g_off[base + i] = run;
        g_cursor[base + i] = run;
        run += local[i];
    }
    if (tid == 1023) g_off[NN] = run;
}
__global__ void k_scatter(const int* __restrict__ edge_index) {
    int e = blockIdx.x * blockDim.x + threadIdx.x;
    if (e >= NE) return;
    int src = edge_index[NE + e];
    int dst = edge_index[e];
    int pos = atomicAdd(&g_cursor[src], 1);
    g_rank[e] = pos;
    g_dstOf[pos] = dst;
}

// ---------------- tf32 helpers ----------------
__device__ __forceinline__ unsigned f2tf32(float x) {
    unsigned u;
    asm("cvt.rna.tf32.f32 %0, %1;" : "=r"(u) : "f"(x));
    return u;
}
__device__ __forceinline__ void mma_tf32(float* c, unsigned a0, unsigned a1, unsigned a2,
                                         unsigned a3, unsigned b0, unsigned b1) {
    asm volatile("mma.sync.aligned.m16n8k8.row.col.f32.tf32.tf32.f32 "
                 "{%0,%1,%2,%3}, {%4,%5,%6,%7}, {%8,%9}, {%0,%1,%2,%3};"
                 : "+f"(c[0]), "+f"(c[1]), "+f"(c[2]), "+f"(c[3])
                 : "r"(a0), "r"(a1), "r"(a2), "r"(a3), "r"(b0), "r"(b1));
}

// ---------------- pipelined 128x128 tf32 GEMM (N,K multiples of 128/16) ----------------
#define AP 132
#define BP 136

template <int M, int N, int K>
__device__ __forceinline__ void mma_gemm128_body(const float* __restrict__ A,
                                                 const float* __restrict__ W,
                                                 const float* __restrict__ Bias,
                                                 float* __restrict__ C) {
    __shared__ unsigned As[2][16][AP];
    __shared__ unsigned Bs[2][16][BP];
    const int tid = threadIdx.x;
    const int lane = tid & 31, w = tid >> 5;
    const int gid = lane >> 2, tig = lane & 3;
    const int wm = (w & 1) * 64;
    const int wn = (w >> 1) * 32;
    const int row0 = blockIdx.y * 128, col0 = blockIdx.x * 128;

    float acc[4][4][4];
    #pragma unroll
    for (int mt = 0; mt < 4; mt++)
        #pragma unroll
        for (int nt = 0; nt < 4; nt++)
            #pragma unroll
            for (int i = 0; i < 4; i++) acc[mt][nt][i] = 0.f;

    float4 pa[2], pb[2];

    // prefetch tile 0
    #pragma unroll
    for (int l = 0; l < 2; l++) {
        int idx = tid + 256 * l;
        int m = idx >> 2, kq = (idx & 3) * 4;
        pa[l] = *reinterpret_cast<const float4*>(&A[(size_t)(row0 + m) * K + kq]);
        int r = idx >> 5, c = (idx & 31) * 4;
        pb[l] = *reinterpret_cast<const float4*>(&W[(size_t)r * N + col0 + c]);
    }
    #pragma unroll
    for (int l = 0; l < 2; l++) {
        int idx = tid + 256 * l;
        int m = idx >> 2, kq = (idx & 3) * 4;
        As[0][kq + 0][m] = f2tf32(pa[l].x);
        As[0][kq + 1][m] = f2tf32(pa[l].y);
        As[0][kq + 2][m] = f2tf32(pa[l].z);
        As[0][kq + 3][m] = f2tf32(pa[l].w);
        int r = idx >> 5, c = (idx & 31) * 4;
        Bs[0][r][c + 0] = f2tf32(pb[l].x);
        Bs[0][r][c + 1] = f2tf32(pb[l].y);
        Bs[0][r][c + 2] = f2tf32(pb[l].z);
        Bs[0][r][c + 3] = f2tf32(pb[l].w);
    }
    __syncthreads();

    const int nIter = K / 16;
    for (int it = 0; it < nIter; it++) {
        int buf = it & 1;
        if (it + 1 < nIter) {
            int k0 = (it + 1) * 16;
            #pragma unroll
            for (int l = 0; l < 2; l++) {
                int idx = tid + 256 * l;
                int m = idx >> 2, kq = (idx & 3) * 4;
                pa[l] = *reinterpret_cast<const float4*>(&A[(size_t)(row0 + m) * K + k0 + kq]);
                int r = idx >> 5, c = (idx & 31) * 4;
                pb[l] = *reinterpret_cast<const float4*>(&W[(size_t)(k0 + r) * N + col0 + c]);
            }
        }
        #pragma unroll
        for (int ks = 0; ks < 2; ks++) {
            int kb = ks * 8;
            unsigned a[4][4], b[4][2];
            #pragma unroll
            for (int mt = 0; mt < 4; mt++) {
                int m0 = wm + mt * 16;
                a[mt][0] = As[buf][kb + tig][m0 + gid];
                a[mt][1] = As[buf][kb + tig][m0 + gid + 8];
                a[mt][2] = As[buf][kb + tig + 4][m0 + gid];
                a[mt][3] = As[buf][kb + tig + 4][m0 + gid + 8];
            }
            #pragma unroll
            for (int nt = 0; nt < 4; nt++) {
                int n0 = wn + nt * 8;
                b[nt][0] = Bs[buf][kb + tig][n0 + gid];
                b[nt][1] = Bs[buf][kb + tig + 4][n0 + gid];
            }
            #pragma unroll
            for (int mt = 0; mt < 4; mt++)
                #pragma unroll
                for (int nt = 0; nt < 4; nt++)
                    mma_tf32(acc[mt][nt], a[mt][0], a[mt][1], a[mt][2], a[mt][3],
                             b[nt][0], b[nt][1]);
        }
        if (it + 1 < nIter) {
            int nb = 1 - buf;
            #pragma unroll
            for (int l = 0; l < 2; l++) {
                int idx = tid + 256 * l;
                int m = idx >> 2, kq = (idx & 3) * 4;
                As[nb][kq + 0][m] = f2tf32(pa[l].x);
                As[nb][kq + 1][m] = f2tf32(pa[l].y);
                As[nb][kq + 2][m] = f2tf32(pa[l].z);
                As[nb][kq + 3][m] = f2tf32(pa[l].w);
                int r = idx >> 5, c = (idx & 31) * 4;
                Bs[nb][r][c + 0] = f2tf32(pb[l].x);
                Bs[nb][r][c + 1] = f2tf32(pb[l].y);
                Bs[nb][r][c + 2] = f2tf32(pb[l].z);
                Bs[nb][r][c + 3] = f2tf32(pb[l].w);
            }
        }
        __syncthreads();
    }
    #pragma unroll
    for (int mt = 0; mt < 4; mt++) {
        #pragma unroll
        for (int i = 0; i < 2; i++) {
            int r = row0 + wm + mt * 16 + gid + i * 8;
            #pragma unroll
            for (int nt = 0; nt < 4; nt++) {
                int cb = col0 + wn + nt * 8 + 2 * tig;
                C[(size_t)r * N + cb]     = acc[mt][nt][i * 2 + 0] + Bias[cb];
                C[(size_t)r * N + cb + 1] = acc[mt][nt][i * 2 + 1] + Bias[cb + 1];
            }
        }
    }
}

__global__ __launch_bounds__(256, 2) void k_gemm_proj(const float* __restrict__ s) {
    mma_gemm128_body<NN, PROJ_COLS, CS>(s, g_Wproj, g_Bproj, g_proj);
}
__global__ __launch_bounds__(256, 2) void k_gemm_out(const float* __restrict__ out_w,
                                                     const float* __restrict__ out_b,
                                                     float* __restrict__ out) {
    mma_gemm128_body<NN, CS, FEAT_COLS>(g_feats, out_w, out_b, out);
}

// ---------------- 128x64 tf32 GEMM (edge: N=44, remapped rows) ----------------
#define AS_STR 130
#define BS_STR 72

template <int M, int N, int K, int LDC, bool REMAP>
__device__ __forceinline__ void mma_gemm_body(const float* __restrict__ A,
                                              const float* __restrict__ W,
                                              const float* __restrict__ Bias,
                                              float* __restrict__ C,
                                              const int* __restrict__ rowmap) {
    __shared__ unsigned As[16][AS_STR];
    __shared__ unsigned Bs[16][BS_STR];
    const int tid = threadIdx.x;
    const int lane = tid & 31, w = tid >> 5;
    const int gid = lane >> 2, tig = lane & 3;
    const int wm = (w & 3) * 32;
    const int wn = (w >> 2) * 32;
    const int row0 = blockIdx.y * 128, col0 = blockIdx.x * 64;

    float c[2][4][4];
    #pragma unroll
    for (int mt = 0; mt < 2; mt++)
        #pragma unroll
        for (int nt = 0; nt < 4; nt++)
            #pragma unroll
            for (int i = 0; i < 4; i++) c[mt][nt][i] = 0.f;

    for (int k0 = 0; k0 < K; k0 += 16) {
        #pragma unroll
        for (int l = 0; l < 2; l++) {
            int idx = tid + 256 * l;
            int r = idx >> 2;
            int kc = (idx & 3) * 4;
            float4 v = *reinterpret_cast<const float4*>(&A[(size_t)(row0 + r) * K + k0 + kc]);
            As[kc + 0][r] = f2tf32(v.x);
            As[kc + 1][r] = f2tf32(v.y);
            As[kc + 2][r] = f2tf32(v.z);
            As[kc + 3][r] = f2tf32(v.w);
        }
        #pragma unroll
        for (int l = 0; l < 4; l++) {
            int idx = tid + 256 * l;
            int r = idx >> 6, cc = idx & 63;
            float v = 0.f;
            if (col0 + cc < N) v = W[(size_t)(k0 + r) * N + col0 + cc];
            Bs[r][cc] = f2tf32(v);
        }
        __syncthreads();
        #pragma unroll
        for (int ks = 0; ks < 2; ks++) {
            int kb = ks * 8;
            unsigned a[2][4], b[4][2];
            #pragma unroll
            for (int mt = 0; mt < 2; mt++) {
                int m0 = wm + mt * 16;
                a[mt][0] = As[kb + tig][m0 + gid];
                a[mt][1] = As[kb + tig][m0 + gid + 8];
                a[mt][2] = As[kb + tig + 4][m0 + gid];
                a[mt][3] = As[kb + tig + 4][m0 + gid + 8];
            }
            #pragma unroll
            for (int nt = 0; nt < 4; nt++) {
                int n0 = wn + nt * 8;
                b[nt][0] = Bs[kb + tig][n0 + gid];
                b[nt][1] = Bs[kb + tig + 4][n0 + gid];
            }
            #pragma unroll
            for (int mt = 0; mt < 2; mt++)
                #pragma unroll
                for (int nt = 0; nt < 4; nt++)
                    mma_tf32(c[mt][nt], a[mt][0], a[mt][1], a[mt][2], a[mt][3],
                             b[nt][0], b[nt][1]);
        }
        __syncthreads();
    }
    #pragma unroll
    for (int mt = 0; mt < 2; mt++) {
        #pragma unroll
        for (int i = 0; i < 2; i++) {
            int r = row0 + wm + mt * 16 + gid + i * 8;
            int crow = REMAP ? rowmap[r] : r;
            #pragma unroll
            for (int nt = 0; nt < 4; nt++) {
                int cbase = col0 + wn + nt * 8 + 2 * tig;
                #pragma unroll
                for (int j = 0; j < 2; j++) {
                    int cc = cbase + j;
                    if (cc < N) C[(size_t)crow * LDC + cc] = c[mt][nt][i * 2 + j] + Bias[cc];
                }
            }
        }
    }
}

__global__ void k_gemm_edge(const float* __restrict__ z) {
    mma_gemm_body<NE, EDGE_COLS, CZ, BPZ_LD, true>(z, g_Wedge, g_Bedge, g_bpzs, g_rank);
}

// ---------------- point transform ----------------
__global__ void k_pointify(const float* __restrict__ rot, const float* __restrict__ trans) {
    int gid = blockIdx.x * blockDim.x + threadIdx.x;
    if (gid >= NN * 192) return;
    int n = gid / 192;
    int p_all = gid % 192;
    const float* R = rot + (size_t)n * 9;
    const float* T = trans + (size_t)n * 3;
    const float* pr = g_proj + (size_t)n * PROJ_COLS;
    if (p_all < 48) {
        int p = p_all;
        float y0 = pr[576 + 0 * 48 + p];
        float y1 = pr[576 + 1 * 48 + p];
        float y2 = pr[576 + 2 * 48 + p];
        #pragma unroll
        for (int i = 0; i < 3; i++) {
            float v = R[i * 3 + 0] * y0 + R[i * 3 + 1] * y1 + R[i * 3 + 2] * y2 + T[i];
            g_qpts[((size_t)n * 48 + p) * 3 + i] = v;
        }
    } else {
        int p = p_all - 48;
        float y0 = pr[720 + 0 * 144 + p];
        float y1 = pr[720 + 1 * 144 + p];
        float y2 = pr[720 + 2 * 144 + p];
        int h = p / 12, j = p % 12;
        #pragma unroll
        for (int i = 0; i < 3; i++) {
            float v = R[i * 3 + 0] * y0 + R[i * 3 + 1] * y1 + R[i * 3 + 2] * y2 + T[i];
            if (j < PQK) g_kpts[((size_t)n * 48 + h * 4 + j) * 3 + i] = v;
            else         g_vpts[((size_t)n * 96 + h * 8 + (j - 4)) * 3 + i] = v;
        }
    }
}

// ---------------- fused per-node: logits + softmax + aggregation ----------------
__device__ __forceinline__ float dot4(float4 a, float4 b) {
    return a.x * b.x + a.y * b.y + a.z * b.z + a.w * b.w;
}

template <bool FAST>
__device__ __forceinline__ void node_body(
    int n, int tid, int beg, int dn,
    const float* __restrict__ mask, const float* __restrict__ head_weights,
    const float* __restrict__ rot, const float* __restrict__ trans,
    float4* s_q, float4* s_qp, float* s_hw, float* s_logit, int* s_dst,
    float* s_red, float* s_amax, float* s_inv, float* sacc) {

    const float4* proj4 = reinterpret_cast<const float4*>(g_proj);
    const float4* kpts4 = reinterpret_cast<const float4*>(g_kpts);
    const float4* vpts4 = reinterpret_cast<const float4*>(g_vpts);
    const float4* bpzs4 = reinterpret_cast<const float4*>(g_bpzs);

    float* lb = FAST ? s_logit : (g_abuf + (size_t)beg * HH);
    const int* dl = FAST ? s_dst : (g_dstOf + beg);

    if (tid < 48) s_q[tid] = proj4[(size_t)n * 288 + tid];
    else if (tid < 84) s_qp[tid - 48] = reinterpret_cast<const float4*>(g_qpts)[(size_t)n * 36 + (tid - 48)];
    else if (tid < 96) s_hw[tid - 84] = 0.5f * S_PT * log1pf(expf(head_weights[tid - 84]));
    if (FAST) {
        for (int i = tid; i < dn; i += 256) s_dst[i] = g_dstOf[beg + i];
    }
    __syncthreads();

    float mn = mask[n];

    if (tid < 252) {
        int h = tid % HH;
        float4 q0 = s_q[h * 4 + 0], q1 = s_q[h * 4 + 1], q2 = s_q[h * 4 + 2], q3 = s_q[h * 4 + 3];
        float4 p0 = s_qp[h * 3 + 0], p1 = s_qp[h * 3 + 1], p2 = s_qp[h * 3 + 2];
        float hwv = s_hw[h];
        for (int i = tid / HH; i < dn; i += 21) {
            int dst = dl[i];
            const float4* kr = proj4 + (size_t)dst * 288 + 48 + h * 8;
            float dot = dot4(q0, kr[0]) + dot4(q1, kr[1]) + dot4(q2, kr[2]) + dot4(q3, kr[3]);
            const float4* kp = kpts4 + (size_t)dst * 36 + h * 3;
            float4 d0 = kp[0], d1 = kp[1], d2 = kp[2];
            float pt = 0.f;
            pt += (p0.x - d0.x) * (p0.x - d0.x) + (p0.y - d0.y) * (p0.y - d0.y)
                + (p0.z - d0.z) * (p0.z - d0.z) + (p0.w - d0.w) * (p0.w - d0.w);
            pt += (p1.x - d1.x) * (p1.x - d1.x) + (p1.y - d1.y) * (p1.y - d1.y)
                + (p1.z - d1.z) * (p1.z - d1.z) + (p1.w - d1.w) * (p1.w - d1.w);
            pt += (p2.x - d2.x) * (p2.x - d2.x) + (p2.y - d2.y) * (p2.y - d2.y)
                + (p2.z - d2.z) * (p2.z - d2.z) + (p2.w - d2.w) * (p2.w - d2.w);
            float b = g_bpzs[(size_t)(beg + i) * BPZ_LD + h];
            float em = INF_C * (mask[dst] * mn - 1.f);
            lb[i * HH + h] = dot * S_QK + S_B * b - hwv * pt + em;
        }
    }
    __syncthreads();

    if (tid < 96) {
        int h = tid % HH, j = tid / HH;
        float m = -INFINITY;
        for (int i = j; i < dn; i += 8) m = fmaxf(m, lb[i * HH + h]);
        s_red[tid] = m;
    }
    __syncthreads();
    if (tid < HH) {
        float m = -INFINITY;
        #pragma unroll
        for (int j = 0; j < 8; j++) m = fmaxf(m, s_red[j * HH + tid]);
        if (!isfinite(m)) m = 0.f;
        s_amax[tid] = m;
    }
    __syncthreads();
    if (tid < 96) {
        int h = tid % HH, j = tid / HH;
        float am = s_amax[h];
        float s = 0.f;
        for (int i = j; i < dn; i += 8) s += expf(lb[i * HH + h] - am);
        s_red[tid] = s;
    }
    __syncthreads();
    if (tid < HH) {
        float s = 0.f;
        #pragma unroll
        for (int j = 0; j < 8; j++) s += s_red[j * HH + tid];
        s_inv[tid] = 1.f / (s + 1e-16f);
    }
    __syncthreads();

    for (int idx = tid; idx < dn * HH; idx += 256) {
        int h = idx % HH;
        lb[idx] = expf(lb[idx] - s_amax[h]) * s_inv[h];
    }
    __syncthreads();

    if (tid < 48) {
        int h = tid >> 2, c4 = tid & 3;
        float4 acc = {0.f, 0.f, 0.f, 0.f};
        for (int i = 0; i < dn; i++) {
            int dst = dl[i];
            float w = lb[i * HH + h];
            float4 v = proj4[(size_t)dst * 288 + 48 + h * 8 + 4 + c4];
            acc.x += w * v.x; acc.y += w * v.y; acc.z += w * v.z; acc.w += w * v.w;
        }
        sacc[tid * 4 + 0] = acc.x; sacc[tid * 4 + 1] = acc.y;
        sacc[tid * 4 + 2] = acc.z; sacc[tid * 4 + 3] = acc.w;
    } else if (tid >= 64 && tid < 136) {
        int c = tid - 64;
        int h = c / 6;
        float4 acc = {0.f, 0.f, 0.f, 0.f};
        for (int i = 0; i < dn; i++) {
            int dst = dl[i];
            float w = lb[i * HH + h];
            float4 v = vpts4[(size_t)dst * 72 + c];
            acc.x += w * v.x; acc.y += w * v.y; acc.z += w * v.z; acc.w += w * v.w;
        }
        sacc[192 + c * 4 + 0] = acc.x; sacc[192 + c * 4 + 1] = acc.y;
        sacc[192 + c * 4 + 2] = acc.z; sacc[192 + c * 4 + 3] = acc.w;
    } else if (tid >= 160 && tid < 184) {
        int c = tid - 160;
        int j = c & 7, hq = c >> 3;
        float4 acc[4];
        #pragma unroll
        for (int r = 0; r < 4; r++) acc[r] = make_float4(0.f, 0.f, 0.f, 0.f);
        for (int i = 0; i < dn; i++) {
            float4 p = bpzs4[(size_t)(beg + i) * 12 + 3 + j];
            #pragma unroll
            for (int r = 0; r < 4; r++) {
                float w = lb[i * HH + hq * 4 + r];
                acc[r].x += w * p.x; acc[r].y += w * p.y;
                acc[r].z += w * p.z; acc[r].w += w * p.w;
            }
        }
        #pragma unroll
        for (int r = 0; r < 4; r++) {
            int base = 480 + (hq * 4 + r) * 32 + j * 4;
            sacc[base + 0] = acc[r].x; sacc[base + 1] = acc[r].y;
            sacc[base + 2] = acc[r].z; sacc[base + 3] = acc[r].w;
        }
    }
    __syncthreads();

    float* f = g_feats + (size_t)n * FEAT_COLS;
    if (tid < 192) f[tid] = sacc[tid];
    for (int t = tid; t < 384; t += 256) f[576 + t] = sacc[480 + t];
    if (tid < 96) {
        int q = tid;
        float g0 = sacc[192 + q * 3 + 0] - trans[(size_t)n * 3 + 0];
        float g1 = sacc[192 + q * 3 + 1] - trans[(size_t)n * 3 + 1];
        float g2 = sacc[192 + q * 3 + 2] - trans[(size_t)n * 3 + 2];
        const float* R = rot + (size_t)n * 9;
        float l0 = R[0] * g0 + R[3] * g1 + R[6] * g2;
        float l1 = R[1] * g0 + R[4] * g1 + R[7] * g2;
        float l2 = R[2] * g0 + R[5] * g1 + R[8] * g2;
        f[192 + q] = l0;
        f[288 + q] = l1;
        f[384 + q] = l2;
        f[480 + q] = sqrtf(l0 * l0 + l1 * l1 + l2 * l2 + 1e-8f);
    }
}

__global__ void k_node(const float* __restrict__ mask, const float* __restrict__ head_weights,
                       const float* __restrict__ rot, const float* __restrict__ trans) {
    __shared__ float4 s_q[48];
    __shared__ float4 s_qp[36];
    __shared__ float  s_hw[12];
    __shared__ float  s_logit[DN_FAST * HH];
    __shared__ int    s_dst[DN_FAST];
    __shared__ float  s_red[96];
    __shared__ float  s_amax[HH], s_inv[HH];
    __shared__ float  sacc[864];

    int n = blockIdx.x;
    int tid = threadIdx.x;
    int beg = g_off[n], dn = g_off[n + 1] - beg;

    if (dn <= DN_FAST)
        node_body<true>(n, tid, beg, dn, mask, head_weights, rot, trans,
                        s_q, s_qp, s_hw, s_logit, s_dst, s_red, s_amax, s_inv, sacc);
    else
        node_body<false>(n, tid, beg, dn, mask, head_weights, rot, trans,
                         s_q, s_qp, s_hw, s_logit, s_dst, s_red, s_amax, s_inv, sacc);
}

// ---------------- launch ----------------
extern "C" void kernel_launch(void* const* d_in, const int* in_sizes, int n_in,
                              void* d_out, int out_size) {
    const float* s          = (const float*)d_in[0];
    const float* z          = (const float*)d_in[1];
    const int*   edge_index = (const int*)  d_in[2];
    const float* rot        = (const float*)d_in[3];
    const float* trans      = (const float*)d_in[4];
    const float* mask       = (const float*)d_in[5];
    const float* q_w        = (const float*)d_in[6];
    const float* q_b        = (const float*)d_in[7];
    const float* kv_w       = (const float*)d_in[8];
    const float* kv_b       = (const float*)d_in[9];
    const float* qp_w       = (const float*)d_in[10];
    const float* qp_b       = (const float*)d_in[11];
    const float* kvp_w      = (const float*)d_in[12];
    const float* kvp_b      = (const float*)d_in[13];
    const float* b_w        = (const float*)d_in[14];
    const float* b_b        = (const float*)d_in[15];
    const float* dz_w       = (const float*)d_in[16];
    const float* dz_b       = (const float*)d_in[17];
    const float* head_w     = (const float*)d_in[18];
    const float* out_w      = (const float*)d_in[19];
    const float* out_b      = (const float*)d_in[20];
    float* out = (float*)d_out;

    k_pack<<<(PACK_TOTAL + 255) / 256, 256>>>(q_w, q_b, kv_w, kv_b, qp_w, qp_b,
                                              kvp_w, kvp_b, b_w, b_b, dz_w, dz_b);
    k_zero_hist<<<NN / 256, 256>>>();
    k_hist<<<NE / 256, 256>>>(edge_index);
    k_scan<<<1, 1024>>>();
    k_scatter<<<NE / 256, 256>>>(edge_index);

    k_gemm_proj<<<dim3(PROJ_COLS / 128, NN / 128), 256>>>(s);
    k_pointify<<<(NN * 192) / 256, 256>>>(rot, trans);
    k_gemm_edge<<<dim3(1, NE / 128), 256>>>(z);
    k_node<<<NN, 256>>>(mask, head_w, rot, trans);
    k_gemm_out<<<dim3(CS / 128, NN / 128), 256>>>(out_w, out_b, out);
}